// round 14
// baseline (speedup 1.0000x reference)
#include <cuda_runtime.h>
#include <cuda_bf16.h>
#include <cstdint>

// ---------------- scratch (static __device__, no allocation) ----------------
__device__ float g_x[8192 * 256];                              // fallback only
__device__ float g_gates[8192 * 768];                          // xg
__device__ __align__(16) __nv_bfloat16 g_aext[8192 * 768];     // A ext buf 1
__device__ __align__(16) __nv_bfloat16 g_aext2[8192 * 768];    // A ext buf 2
__device__ __align__(16) __nv_bfloat16 g_bext0[256 * 768];     // embed_w ext
__device__ __align__(16) __nv_bfloat16 g_bext1[768 * 768];     // Wih l0 ext
__device__ __align__(16) __nv_bfloat16 g_bext2[768 * 768];     // Wih l1 ext

#define Bsz 128
#define Ssz 64
#define Psz 32
#define Dsz 256
#define Hsz 128
#define KEXT 768

#define FMA2(acc, a, b) \
    asm("fma.rn.f32x2 %0, %1, %2, %0;" : "+l"(acc) : "l"(a), "l"(b))
__device__ __forceinline__ float pk_lo(unsigned long long p) {
    return __uint_as_float((unsigned)(p & 0xffffffffull));
}
__device__ __forceinline__ float pk_hi(unsigned long long p) {
    return __uint_as_float((unsigned)(p >> 32));
}

// MUFU.TANH-based activations
__device__ __forceinline__ float ftanh(float x) {
    float r;
    asm("tanh.approx.f32 %0, %1;" : "=f"(r) : "f"(x));
    return r;
}
__device__ __forceinline__ float fsig(float x) {
    return 0.5f * ftanh(0.5f * x) + 0.5f;
}

// hi/lo bf16 split store for A rows: [hi | lo | hi] at +0,+256,+512
__device__ __forceinline__ void store_ext2(__nv_bfloat16* base, float v0, float v1) {
    __nv_bfloat16 h0 = __float2bfloat16(v0), h1 = __float2bfloat16(v1);
    __nv_bfloat16 l0 = __float2bfloat16(v0 - __bfloat162float(h0));
    __nv_bfloat16 l1 = __float2bfloat16(v1 - __bfloat162float(h1));
    __nv_bfloat162 hh; hh.x = h0; hh.y = h1;
    __nv_bfloat162 ll; ll.x = l0; ll.y = l1;
    *(__nv_bfloat162*)(base)       = hh;
    *(__nv_bfloat162*)(base + 256) = ll;
    *(__nv_bfloat162*)(base + 512) = hh;
}

// ---------------- baseline-PTX tensor helpers ----------------
__device__ __forceinline__ void ldmx4(uint32_t* r, uint32_t addr) {
    asm volatile("ldmatrix.sync.aligned.m8n8.x4.shared.b16 {%0,%1,%2,%3}, [%4];"
                 : "=r"(r[0]), "=r"(r[1]), "=r"(r[2]), "=r"(r[3]) : "r"(addr));
}
__device__ __forceinline__ void mma_bf16(float* d, const uint32_t* a,
                                         const uint32_t* b) {
    asm volatile(
        "mma.sync.aligned.m16n8k16.row.col.f32.bf16.bf16.f32 "
        "{%0,%1,%2,%3}, {%4,%5,%6,%7}, {%8,%9}, {%0,%1,%2,%3};"
        : "+f"(d[0]), "+f"(d[1]), "+f"(d[2]), "+f"(d[3])
        : "r"(a[0]), "r"(a[1]), "r"(a[2]), "r"(a[3]), "r"(b[0]), "r"(b[1]));
}
#define CP_ASYNC16(sm, gm) \
    asm volatile("cp.async.cg.shared.global [%0], [%1], 16;" \
                 :: "r"(sm), "l"(gm))
#define CP_COMMIT() asm volatile("cp.async.commit_group;" ::: "memory")
#define CP_WAIT1()  asm volatile("cp.async.wait_group 1;" ::: "memory")
#define CP_WAIT0()  asm volatile("cp.async.wait_group 0;" ::: "memory")

__device__ __forceinline__ uint32_t smem_u32(const void* p) {
    uint32_t a;
    asm("{ .reg .u64 t; cvta.to.shared.u64 t, %1; cvt.u32.u64 %0, t; }"
        : "=r"(a) : "l"(p));
    return a;
}

// =====================================================================
// Kernel 1: fused prep. Blocks [0,8192): conv + weighted event sum ->
// A_ext. Blocks [8192,9984): B weight conversions (3 matrices).
// =====================================================================
__global__ __launch_bounds__(256)
void prep_kernel(const float* __restrict__ in, const float* __restrict__ conv_w,
                 const float* __restrict__ conv_b, __nv_bfloat16* __restrict__ aext,
                 const float* __restrict__ we, const float* __restrict__ w0,
                 const float* __restrict__ w1, __nv_bfloat16* __restrict__ b0,
                 __nv_bfloat16* __restrict__ b1, __nv_bfloat16* __restrict__ b2)
{
    __shared__ __align__(16) float tile[Psz * Dsz];
    __shared__ float cw[Dsz];
    __shared__ float sp[Psz];

    const int tid = threadIdx.x;

    if (blockIdx.x >= 8192) {
        const int r = blockIdx.x - 8192;
        const float* src; __nv_bfloat16* dst; int row;
        if (r < 256)       { src = we; row = r;        dst = b0; }
        else if (r < 1024) { src = w0; row = r - 256;  dst = b1; }
        else               { src = w1; row = r - 1024; dst = b2; }
        float x = src[(size_t)row * 256 + tid];
        __nv_bfloat16 h = __float2bfloat16(x);
        __nv_bfloat16 l = __float2bfloat16(x - __bfloat162float(h));
        __nv_bfloat16* o = dst + (size_t)row * KEXT;
        o[tid] = h; o[256 + tid] = h; o[512 + tid] = l;
        return;
    }

    const float* src = in + (size_t)blockIdx.x * (Psz * Dsz);

    cw[tid] = conv_w[tid];
    const float4* src4 = (const float4*)src;
    float4* tile4 = (float4*)tile;
#pragma unroll
    for (int i = 0; i < 8; i++)
        tile4[tid + i * 256] = src4[tid + i * 256];
    __syncthreads();

    const int warp = tid >> 5, lane = tid & 31;
#pragma unroll
    for (int r = 0; r < 4; r++) {
        int p = warp * 4 + r;
        float acc = 0.f;
#pragma unroll
        for (int j = 0; j < 8; j++)
            acc += tile[p * Dsz + lane + j * 32] * cw[lane + j * 32];
#pragma unroll
        for (int o = 16; o; o >>= 1)
            acc += __shfl_xor_sync(0xffffffffu, acc, o);
        if (lane == 0) sp[p] = acc + conv_b[0];
    }
    __syncthreads();

    float acc = 0.f;
#pragma unroll
    for (int p = 0; p < Psz; p++)
        acc += sp[p] * tile[p * Dsz + tid];

    __nv_bfloat16 h = __float2bfloat16(acc);
    __nv_bfloat16 l = __float2bfloat16(acc - __bfloat162float(h));
    __nv_bfloat16* o = aext + (size_t)blockIdx.x * KEXT;
    o[tid] = h; o[256 + tid] = l; o[512 + tid] = h;
}

// =====================================================================
// Kernel 2: mma.sync bf16 GEMM, generalized over BN tile (64 or 96).
// BM=128, BK=32, 256 thr (8 warps: 4m x 2n), 3-stage cp.async.
// BNT=96 for the gates GEMMs (grid 8x64=512 blocks -> 1.15 waves @3/SM)
// BNT=64 for embed (proven config).
// =====================================================================
#define GBM 128
#define LDE 40
#define ABYTES (128 * LDE * 2)          // 10240
#define NSTEP 24

template<int BNT, bool AEXT, bool BIAS>
__global__ __launch_bounds__(256, (BNT == 64 ? 4 : 3))
void tgemm_mma(const __nv_bfloat16* __restrict__ Aext,
               const __nv_bfloat16* __restrict__ Bext,
               const float* __restrict__ bias, float* __restrict__ Cf,
               __nv_bfloat16* __restrict__ Ce, int Ntot)
{
    constexpr int BBYTES = BNT * LDE * 2;
    constexpr int STAGEB = ABYTES + BBYTES;
    constexpr int WN = BNT / 2;          // cols per warp
    constexpr int FN = WN / 8;           // n-fragments per warp
    constexpr int NG = WN / 16;          // ldmatrix groups per warp

    extern __shared__ __align__(16) uint8_t smem[];

    const int tid = threadIdx.x;
    const int wid = tid >> 5, lane = tid & 31;
    const int bm = blockIdx.y * GBM;
    const int bn = blockIdx.x * BNT;

    const uint32_t smBase = smem_u32(smem);

    const int warp_m = wid >> 1;
    const int warp_n = wid & 1;

    float acc[2][FN][4];
#pragma unroll
    for (int i = 0; i < 2; i++)
#pragma unroll
        for (int j = 0; j < FN; j++)
#pragma unroll
            for (int q = 0; q < 4; q++) acc[i][j][q] = 0.f;

    const int arow = tid >> 2, aseg = tid & 3;
    const int lrow = lane & 15;
    const int lcol = (lane >> 4) * 16;

#define LOAD_TILE(step, buf) do {                                              \
    int kt = (step) * 32;                                                      \
    uint32_t a_s = smBase + (buf) * STAGEB;                                    \
    uint32_t b_s = a_s + ABYTES;                                               \
    CP_ASYNC16(a_s + arow * 80 + aseg * 16,                                    \
               Aext + (size_t)(bm + arow) * KEXT + kt + aseg * 8);             \
    CP_ASYNC16(a_s + (arow + 64) * 80 + aseg * 16,                             \
               Aext + (size_t)(bm + arow + 64) * KEXT + kt + aseg * 8);        \
    _Pragma("unroll")                                                          \
    for (int u = tid; u < BNT * 4; u += 256) {                                 \
        int brow = u >> 2, bseg = u & 3;                                       \
        CP_ASYNC16(b_s + brow * 80 + bseg * 16,                                \
                   Bext + (size_t)(bn + brow) * KEXT + kt + bseg * 8);         \
    }                                                                          \
} while (0)

    LOAD_TILE(0, 0); CP_COMMIT();
    LOAD_TILE(1, 1); CP_COMMIT();

    int buf = 0;
    for (int s = 0; s < NSTEP; s++) {
        if (s == NSTEP - 1) { CP_WAIT0(); } else { CP_WAIT1(); }
        __syncthreads();

        const uint32_t aBase = smBase + buf * STAGEB
                             + (warp_m * 32 + lrow) * 80 + lcol;
        const uint32_t bBase = smBase + buf * STAGEB + ABYTES
                             + (warp_n * WN + lrow) * 80 + lcol;
#pragma unroll
        for (int ks = 0; ks < 2; ks++) {
            uint32_t a0[4], a1[4];
            ldmx4(a0, aBase + ks * 32);
            ldmx4(a1, aBase + 16 * 80 + ks * 32);
#pragma unroll
            for (int ng = 0; ng < NG; ng++) {
                uint32_t bR[4];
                ldmx4(bR, bBase + ng * 16 * 80 + ks * 32);
                uint32_t bf0[2] = {bR[0], bR[2]};
                uint32_t bf1[2] = {bR[1], bR[3]};
                mma_bf16(acc[0][2 * ng],     a0, bf0);
                mma_bf16(acc[0][2 * ng + 1], a0, bf1);
                mma_bf16(acc[1][2 * ng],     a1, bf0);
                mma_bf16(acc[1][2 * ng + 1], a1, bf1);
            }
        }
        if (s + 2 < NSTEP) { LOAD_TILE(s + 2, (s + 2) % 3); CP_COMMIT(); }
        buf = (buf + 1 == 3) ? 0 : buf + 1;
    }
#undef LOAD_TILE

    const int qr = lane >> 2;
    const int qc = (lane & 3) * 2;
#pragma unroll
    for (int fm = 0; fm < 2; fm++) {
#pragma unroll
        for (int fn = 0; fn < FN; fn++) {
            const int m0 = bm + warp_m * 32 + fm * 16 + qr;
            const int n0 = bn + warp_n * WN + fn * 8 + qc;
            float b0 = 0.f, b1 = 0.f;
            if (BIAS) { b0 = bias[n0]; b1 = bias[n0 + 1]; }
            float v0 = acc[fm][fn][0] + b0;
            float v1 = acc[fm][fn][1] + b1;
            float v2 = acc[fm][fn][2] + b0;
            float v3 = acc[fm][fn][3] + b1;
            if (AEXT) {
                v0 = fminf(1.f, fmaxf(-1.f, v0));
                v1 = fminf(1.f, fmaxf(-1.f, v1));
                v2 = fminf(1.f, fmaxf(-1.f, v2));
                v3 = fminf(1.f, fmaxf(-1.f, v3));
                store_ext2(Ce + (size_t)m0 * KEXT + n0, v0, v1);
                store_ext2(Ce + (size_t)(m0 + 8) * KEXT + n0, v2, v3);
            } else {
                *(float2*)&Cf[(size_t)m0 * Ntot + n0]       = make_float2(v0, v1);
                *(float2*)&Cf[(size_t)(m0 + 8) * Ntot + n0] = make_float2(v2, v3);
            }
        }
    }
}

// =====================================================================
// Kernel 3a: GRU scan for the EXT=1 launch (R10 measured-best structure:
// 2-way K-split, 384 thr, gh smem, two barriers), with the EXT global
// stores moved AFTER the bottom barrier so STG issue overlaps the next
// step's matvec.
// =====================================================================
__global__ __launch_bounds__(384, 1)
void gru_scan_ext(const float* __restrict__ gates, const float* __restrict__ Whh,
                  const float* __restrict__ bhh, __nv_bfloat16* __restrict__ outE)
{
    const int dir = blockIdx.x >> 6;
    const int bpair = blockIdx.x & 63;
    const int b0 = bpair * 2;
    const int g = threadIdx.x;
    const int rr = g >> 1;          // 0..191
    const int a  = g & 1;           // k-half

    const float* Wbase = Whh + (size_t)dir * 384 * 128;
    const ulonglong2* W0 = (const ulonglong2*)(Wbase + (size_t)rr * 128 + a * 64);
    const ulonglong2* W1 = (const ulonglong2*)(Wbase + (size_t)(rr + 192) * 128 + a * 64);
    unsigned long long w0[32], w1[32];
#pragma unroll
    for (int i = 0; i < 16; i++) {
        ulonglong2 t0 = W0[i];
        ulonglong2 t1 = W1[i];
        w0[2 * i] = t0.x; w0[2 * i + 1] = t0.y;
        w1[2 * i] = t1.x; w1[2 * i + 1] = t1.y;
    }
    const float bias0 = bhh[dir * 384 + rr];
    const float bias1 = bhh[dir * 384 + rr + 192];

    __shared__ __align__(16) float h0[Hsz];
    __shared__ __align__(16) float h1[Hsz];
    __shared__ float gh0[384];
    __shared__ float gh1[384];

    if (g < Hsz) { h0[g] = 0.f; h1[g] = 0.f; }
    __syncthreads();

    const int j = g & 127;
    const int isb1 = (g >= 128 && g < 256) ? 1 : 0;
    const int bc = b0 + isb1;

    const ulonglong2* hv0 = (const ulonglong2*)(h0 + a * 64);
    const ulonglong2* hv1 = (const ulonglong2*)(h1 + a * 64);

    for (int t_ = 0; t_ < Ssz; t_++) {
        const int t = dir ? (Ssz - 1 - t_) : t_;

        float xr = 0.f, xz = 0.f, xn = 0.f;
        if (g < 256) {
            const float* gb = gates + ((size_t)(bc * Ssz + t)) * 768 + dir * 384;
            xr = gb[j];
            xz = gb[128 + j];
            xn = gb[256 + j];
        }

        unsigned long long c00 = 0ull, c01 = 0ull, c10 = 0ull, c11 = 0ull;
#pragma unroll
        for (int i = 0; i < 16; i++) {
            ulonglong2 p = hv0[i];
            ulonglong2 q = hv1[i];
            FMA2(c00, w0[2 * i],     p.x);
            FMA2(c00, w0[2 * i + 1], p.y);
            FMA2(c01, w1[2 * i],     p.x);
            FMA2(c01, w1[2 * i + 1], p.y);
            FMA2(c10, w0[2 * i],     q.x);
            FMA2(c10, w0[2 * i + 1], q.y);
            FMA2(c11, w1[2 * i],     q.x);
            FMA2(c11, w1[2 * i + 1], q.y);
        }
        float s00 = pk_lo(c00) + pk_hi(c00);
        float s01 = pk_lo(c01) + pk_hi(c01);
        float s10 = pk_lo(c10) + pk_hi(c10);
        float s11 = pk_lo(c11) + pk_hi(c11);
        s00 += __shfl_xor_sync(0xffffffffu, s00, 1);
        s01 += __shfl_xor_sync(0xffffffffu, s01, 1);
        s10 += __shfl_xor_sync(0xffffffffu, s10, 1);
        s11 += __shfl_xor_sync(0xffffffffu, s11, 1);
        if (a == 0) {
            gh0[rr]       = s00 + bias0;
            gh0[rr + 192] = s01 + bias1;
            gh1[rr]       = s10 + bias0;
            gh1[rr + 192] = s11 + bias1;
        }
        __syncthreads();

        float hnew = 0.f;
        if (g < 256) {
            float* h  = isb1 ? h1 : h0;
            float* gh = isb1 ? gh1 : gh0;
            float r = fsig(xr + gh[j]);
            float z = fsig(xz + gh[128 + j]);
            float n = ftanh(xn + r * gh[256 + j]);
            hnew = n + z * (h[j] - n);
            h[j] = hnew;
        }
        __syncthreads();

        // EXT stores AFTER the barrier: overlap next step's matvec
        if (g < 256) {
            __nv_bfloat16 hh = __float2bfloat16(hnew);
            __nv_bfloat16 ll = __float2bfloat16(hnew - __bfloat162float(hh));
            __nv_bfloat16* o = outE + ((size_t)(bc * Ssz + t)) * KEXT
                             + dir * 128 + j;
            o[0] = hh; o[256] = ll; o[512] = hh;
        }
    }
}

// =====================================================================
// Kernel 3b: GRU scan for the EXT=0 launch (R11 measured-best:
// gate-fused, 256 thr, one barrier, ping-pong h). Writes fp32 states.
// =====================================================================
__global__ __launch_bounds__(256, 1)
void gru_scan_fused(const float* __restrict__ gates, const float* __restrict__ Whh,
                    const float* __restrict__ bhh, float* __restrict__ outF)
{
    const int dir = blockIdx.x >> 6;
    const int bpair = blockIdx.x & 63;
    const int b0 = bpair * 2;
    const int g = threadIdx.x;
    const int j = g >> 1;
    const int a = g & 1;

    const float* Wb = Whh + (size_t)dir * 384 * 128;
    const ulonglong2* Wr = (const ulonglong2*)(Wb + (size_t)j * 128 + a * 64);
    const ulonglong2* Wz = (const ulonglong2*)(Wb + (size_t)(128 + j) * 128 + a * 64);
    const ulonglong2* Wn = (const ulonglong2*)(Wb + (size_t)(256 + j) * 128 + a * 64);
    unsigned long long wr[32], wz[32], wn[32];
#pragma unroll
    for (int i = 0; i < 16; i++) {
        ulonglong2 tr = Wr[i], tz = Wz[i], tn = Wn[i];
        wr[2 * i] = tr.x; wr[2 * i + 1] = tr.y;
        wz[2 * i] = tz.x; wz[2 * i + 1] = tz.y;
        wn[2 * i] = tn.x; wn[2 * i + 1] = tn.y;
    }
    const float br = bhh[dir * 384 + j];
    const float bz = bhh[dir * 384 + 128 + j];
    const float bn = bhh[dir * 384 + 256 + j];

    __shared__ __align__(16) float hsm[2][2][Hsz];

    if (g < Hsz) { hsm[0][0][g] = 0.f; hsm[0][1][g] = 0.f; }
    __syncthreads();

    float hprev0 = 0.f, hprev1 = 0.f;

    const float* gbase0 = gates + ((size_t)(b0 * Ssz)) * 768 + dir * 384;
    const float* gbase1 = gates + ((size_t)((b0 + 1) * Ssz)) * 768 + dir * 384;

    for (int t_ = 0; t_ < Ssz; t_++) {
        const int t = dir ? (Ssz - 1 - t_) : t_;
        const int p = t_ & 1;

        const float* gb0 = gbase0 + (size_t)t * 768;
        const float* gb1 = gbase1 + (size_t)t * 768;
        float xr0 = gb0[j], xz0 = gb0[128 + j], xn0 = gb0[256 + j];
        float xr1 = gb1[j], xz1 = gb1[128 + j], xn1 = gb1[256 + j];

        const ulonglong2* hv0 = (const ulonglong2*)(&hsm[p][0][a * 64]);
        const ulonglong2* hv1 = (const ulonglong2*)(&hsm[p][1][a * 64]);

        unsigned long long cr0 = 0ull, cz0 = 0ull, cn0 = 0ull;
        unsigned long long cr1 = 0ull, cz1 = 0ull, cn1 = 0ull;
#pragma unroll
        for (int i = 0; i < 16; i++) {
            ulonglong2 hp = hv0[i];
            ulonglong2 hq = hv1[i];
            FMA2(cr0, wr[2 * i],     hp.x); FMA2(cr0, wr[2 * i + 1], hp.y);
            FMA2(cz0, wz[2 * i],     hp.x); FMA2(cz0, wz[2 * i + 1], hp.y);
            FMA2(cn0, wn[2 * i],     hp.x); FMA2(cn0, wn[2 * i + 1], hp.y);
            FMA2(cr1, wr[2 * i],     hq.x); FMA2(cr1, wr[2 * i + 1], hq.y);
            FMA2(cz1, wz[2 * i],     hq.x); FMA2(cz1, wz[2 * i + 1], hq.y);
            FMA2(cn1, wn[2 * i],     hq.x); FMA2(cn1, wn[2 * i + 1], hq.y);
        }
        float sr0 = pk_lo(cr0) + pk_hi(cr0);
        float sz0 = pk_lo(cz0) + pk_hi(cz0);
        float sn0 = pk_lo(cn0) + pk_hi(cn0);
        float sr1 = pk_lo(cr1) + pk_hi(cr1);
        float sz1 = pk_lo(cz1) + pk_hi(cz1);
        float sn1 = pk_lo(cn1) + pk_hi(cn1);
        sr0 += __shfl_xor_sync(0xffffffffu, sr0, 1);
        sz0 += __shfl_xor_sync(0xffffffffu, sz0, 1);
        sn0 += __shfl_xor_sync(0xffffffffu, sn0, 1);
        sr1 += __shfl_xor_sync(0xffffffffu, sr1, 1);
        sz1 += __shfl_xor_sync(0xffffffffu, sz1, 1);
        sn1 += __shfl_xor_sync(0xffffffffu, sn1, 1);

        float r0 = fsig(xr0 + sr0 + br);
        float z0 = fsig(xz0 + sz0 + bz);
        float n0 = ftanh(xn0 + r0 * (sn0 + bn));
        float h0n = n0 + z0 * (hprev0 - n0);
        float r1 = fsig(xr1 + sr1 + br);
        float z1 = fsig(xz1 + sz1 + bz);
        float n1 = ftanh(xn1 + r1 * (sn1 + bn));
        float h1n = n1 + z1 * (hprev1 - n1);
        hprev0 = h0n; hprev1 = h1n;

        float hw = a ? h1n : h0n;
        hsm[p ^ 1][a][j] = hw;
        const int bc = b0 + a;
        outF[((size_t)(bc * Ssz + t)) * 256 + dir * 128 + j] = hw;
        __syncthreads();
    }
}

// =====================================================================
// Kernel 4: epilogue (alpha == 1 exactly: softmax over singleton axis)
// =====================================================================
__global__ __launch_bounds__(256)
void epilogue_kernel(const float* __restrict__ states, const float* __restrict__ lin_w,
                     const float* __restrict__ lin_b, float* __restrict__ out_out,
                     float* __restrict__ out_ctx, float* __restrict__ out_alpha)
{
    __shared__ float ctx[256];
    __shared__ float logits[2];
    const int b = blockIdx.x;
    const int tid = threadIdx.x;

    const float* sb = states + (size_t)b * Ssz * 256;
    float acc = 0.f;
#pragma unroll
    for (int s = 0; s < Ssz; s++)
        acc += sb[s * 256 + tid];
    ctx[tid] = acc;
    out_ctx[(size_t)b * 256 + tid] = acc;
    if (tid < Ssz) out_alpha[(size_t)b * Ssz + tid] = 1.0f;
    __syncthreads();

    if (tid < 64) {
        const int o = tid >> 5, lane = tid & 31;
        float p = 0.f;
#pragma unroll
        for (int k = 0; k < 8; k++)
            p += ctx[lane + k * 32] * lin_w[o * 256 + lane + k * 32];
#pragma unroll
        for (int off = 16; off; off >>= 1)
            p += __shfl_xor_sync(0xffffffffu, p, off);
        if (lane == 0) logits[o] = p + lin_b[o];
    }
    __syncthreads();
    if (tid == 0) {
        float l0 = logits[0], l1 = logits[1];
        float m = fmaxf(l0, l1);
        float e0 = expf(l0 - m), e1 = expf(l1 - m);
        float inv = 1.0f / (e0 + e1);
        out_out[b * 2 + 0] = e0 * inv;
        out_out[b * 2 + 1] = e1 * inv;
    }
}

// =====================================================================
// launcher
// =====================================================================
extern "C" void kernel_launch(void* const* d_in, const int* in_sizes, int n_in,
                              void* d_out, int out_size)
{
    const float* inputs  = (const float*)d_in[0];
    const float* conv_w  = (const float*)d_in[1];
    const float* conv_b  = (const float*)d_in[2];
    const float* embed_w = (const float*)d_in[3];
    const float* Wih     = (const float*)d_in[4];
    const float* Whh     = (const float*)d_in[5];
    const float* bih     = (const float*)d_in[6];
    const float* bhh     = (const float*)d_in[7];
    const float* lin_w   = (const float*)d_in[9];
    const float* lin_b   = (const float*)d_in[10];

    float* out_base = (float*)d_out;
    const int total_expected = 256 + 8192 * 256 + 128 * 256 + 128 * 64;
    float* out_out    = out_base;
    float* out_states = out_base + 256;
    float* out_ctx    = out_states + 8192 * 256;
    float* out_alpha  = out_ctx + 128 * 256;
    const bool full = (out_size >= total_expected);

    float *px, *pgates;
    __nv_bfloat16 *paext, *paext2, *pb0, *pb1, *pb2;
    cudaGetSymbolAddress((void**)&px, g_x);
    cudaGetSymbolAddress((void**)&pgates, g_gates);
    cudaGetSymbolAddress((void**)&paext, g_aext);
    cudaGetSymbolAddress((void**)&paext2, g_aext2);
    cudaGetSymbolAddress((void**)&pb0, g_bext0);
    cudaGetSymbolAddress((void**)&pb1, g_bext1);
    cudaGetSymbolAddress((void**)&pb2, g_bext2);

    const int DYN64 = 3 * (ABYTES + 64 * LDE * 2);   // 46080
    const int DYN96 = 3 * (ABYTES + 96 * LDE * 2);   // 53760

    cudaFuncSetAttribute(tgemm_mma<64, true, false>,
                         cudaFuncAttributeMaxDynamicSharedMemorySize, DYN64);
    cudaFuncSetAttribute(tgemm_mma<96, false, true>,
                         cudaFuncAttributeMaxDynamicSharedMemorySize, DYN96);
    cudaFuncSetAttribute(tgemm_mma<64, true, false>,
                         cudaFuncAttributePreferredSharedMemoryCarveout, 100);
    cudaFuncSetAttribute(tgemm_mma<96, false, true>,
                         cudaFuncAttributePreferredSharedMemoryCarveout, 100);

    // 1) conv + weighted sum -> A_ext  AND  all 3 weight conversions
    prep_kernel<<<8192 + 1792, 256>>>(inputs, conv_w, conv_b, paext,
                                      embed_w, Wih, Wih + (size_t)2 * 384 * 256,
                                      pb0, pb1, pb2);

    // 2) embed + hardtanh (epilogue writes A_ext2); BN=64 proven config
    tgemm_mma<64, true, false><<<dim3(256 / 64, 8192 / GBM), 256, DYN64>>>(
        paext, pb0, nullptr, nullptr, paext2, 256);

    // 3) layer 0: gates GEMM (BN=96, 512 blocks) -> gru (writes A_ext)
    tgemm_mma<96, false, true><<<dim3(768 / 96, 8192 / GBM), 256, DYN96>>>(
        paext2, pb1, bih, pgates, nullptr, 768);
    gru_scan_ext<<<128, 384>>>(pgates, Whh, bhh, paext);

    // 4) layer 1: gates GEMM -> gru (writes fp32 states)
    tgemm_mma<96, false, true><<<dim3(768 / 96, 8192 / GBM), 256, DYN96>>>(
        paext, pb2, bih + 2 * 384, pgates, nullptr, 768);
    float* states_dst = full ? out_states : px;
    gru_scan_fused<<<128, 256>>>(pgates, Whh + (size_t)2 * 384 * 128,
                                 bhh + 2 * 384, states_dst);

    // 5) epilogue
    if (full) {
        epilogue_kernel<<<Bsz, 256>>>(states_dst, lin_w, lin_b,
                                      out_out, out_ctx, out_alpha);
    } else {
        epilogue_kernel<<<Bsz, 256>>>(states_dst, lin_w, lin_b,
                                      out_out, px, px + 128 * 256);
    }
}

// round 15
// speedup vs baseline: 1.0135x; 1.0135x over previous
#include <cuda_runtime.h>
#include <cuda_bf16.h>
#include <cstdint>

// ---------------- scratch (static __device__, no allocation) ----------------
__device__ float g_x[8192 * 256];                              // fallback only
__device__ float g_ctx[128 * 256];                             // fallback ctx
__device__ float g_gates[8192 * 768];                          // xg
__device__ __align__(16) __nv_bfloat16 g_aext[8192 * 768];     // A ext buf 1
__device__ __align__(16) __nv_bfloat16 g_aext2[8192 * 768];    // A ext buf 2
__device__ __align__(16) __nv_bfloat16 g_bext0[256 * 768];     // embed_w ext
__device__ __align__(16) __nv_bfloat16 g_bext1[768 * 768];     // Wih l0 ext
__device__ __align__(16) __nv_bfloat16 g_bext2[768 * 768];     // Wih l1 ext

#define Bsz 128
#define Ssz 64
#define Psz 32
#define Dsz 256
#define Hsz 128
#define KEXT 768

#define FMA2(acc, a, b) \
    asm("fma.rn.f32x2 %0, %1, %2, %0;" : "+l"(acc) : "l"(a), "l"(b))
__device__ __forceinline__ float pk_lo(unsigned long long p) {
    return __uint_as_float((unsigned)(p & 0xffffffffull));
}
__device__ __forceinline__ float pk_hi(unsigned long long p) {
    return __uint_as_float((unsigned)(p >> 32));
}

// MUFU.TANH-based activations
__device__ __forceinline__ float ftanh(float x) {
    float r;
    asm("tanh.approx.f32 %0, %1;" : "=f"(r) : "f"(x));
    return r;
}
__device__ __forceinline__ float fsig(float x) {
    return 0.5f * ftanh(0.5f * x) + 0.5f;
}

// hi/lo bf16 split store for A rows: [hi | lo | hi] at +0,+256,+512
__device__ __forceinline__ void store_ext2(__nv_bfloat16* base, float v0, float v1) {
    __nv_bfloat16 h0 = __float2bfloat16(v0), h1 = __float2bfloat16(v1);
    __nv_bfloat16 l0 = __float2bfloat16(v0 - __bfloat162float(h0));
    __nv_bfloat16 l1 = __float2bfloat16(v1 - __bfloat162float(h1));
    __nv_bfloat162 hh; hh.x = h0; hh.y = h1;
    __nv_bfloat162 ll; ll.x = l0; ll.y = l1;
    *(__nv_bfloat162*)(base)       = hh;
    *(__nv_bfloat162*)(base + 256) = ll;
    *(__nv_bfloat162*)(base + 512) = hh;
}

// ---------------- baseline-PTX tensor helpers ----------------
__device__ __forceinline__ void ldmx4(uint32_t* r, uint32_t addr) {
    asm volatile("ldmatrix.sync.aligned.m8n8.x4.shared.b16 {%0,%1,%2,%3}, [%4];"
                 : "=r"(r[0]), "=r"(r[1]), "=r"(r[2]), "=r"(r[3]) : "r"(addr));
}
__device__ __forceinline__ void mma_bf16(float* d, const uint32_t* a,
                                         const uint32_t* b) {
    asm volatile(
        "mma.sync.aligned.m16n8k16.row.col.f32.bf16.bf16.f32 "
        "{%0,%1,%2,%3}, {%4,%5,%6,%7}, {%8,%9}, {%0,%1,%2,%3};"
        : "+f"(d[0]), "+f"(d[1]), "+f"(d[2]), "+f"(d[3])
        : "r"(a[0]), "r"(a[1]), "r"(a[2]), "r"(a[3]), "r"(b[0]), "r"(b[1]));
}
#define CP_ASYNC16(sm, gm) \
    asm volatile("cp.async.cg.shared.global [%0], [%1], 16;" \
                 :: "r"(sm), "l"(gm))
#define CP_COMMIT() asm volatile("cp.async.commit_group;" ::: "memory")
#define CP_WAIT1()  asm volatile("cp.async.wait_group 1;" ::: "memory")
#define CP_WAIT0()  asm volatile("cp.async.wait_group 0;" ::: "memory")

__device__ __forceinline__ uint32_t smem_u32(const void* p) {
    uint32_t a;
    asm("{ .reg .u64 t; cvta.to.shared.u64 t, %1; cvt.u32.u64 %0, t; }"
        : "=r"(a) : "l"(p));
    return a;
}

// =====================================================================
// Kernel 1: fused prep. Blocks [0,8192): conv + weighted event sum ->
// A_ext. Blocks [8192,9984): B weight conversions (3 matrices).
// =====================================================================
__global__ __launch_bounds__(256)
void prep_kernel(const float* __restrict__ in, const float* __restrict__ conv_w,
                 const float* __restrict__ conv_b, __nv_bfloat16* __restrict__ aext,
                 const float* __restrict__ we, const float* __restrict__ w0,
                 const float* __restrict__ w1, __nv_bfloat16* __restrict__ b0,
                 __nv_bfloat16* __restrict__ b1, __nv_bfloat16* __restrict__ b2)
{
    __shared__ __align__(16) float tile[Psz * Dsz];
    __shared__ float cw[Dsz];
    __shared__ float sp[Psz];

    const int tid = threadIdx.x;

    if (blockIdx.x >= 8192) {
        const int r = blockIdx.x - 8192;
        const float* src; __nv_bfloat16* dst; int row;
        if (r < 256)       { src = we; row = r;        dst = b0; }
        else if (r < 1024) { src = w0; row = r - 256;  dst = b1; }
        else               { src = w1; row = r - 1024; dst = b2; }
        float x = src[(size_t)row * 256 + tid];
        __nv_bfloat16 h = __float2bfloat16(x);
        __nv_bfloat16 l = __float2bfloat16(x - __bfloat162float(h));
        __nv_bfloat16* o = dst + (size_t)row * KEXT;
        o[tid] = h; o[256 + tid] = h; o[512 + tid] = l;
        return;
    }

    const float* src = in + (size_t)blockIdx.x * (Psz * Dsz);

    cw[tid] = conv_w[tid];
    const float4* src4 = (const float4*)src;
    float4* tile4 = (float4*)tile;
#pragma unroll
    for (int i = 0; i < 8; i++)
        tile4[tid + i * 256] = src4[tid + i * 256];
    __syncthreads();

    const int warp = tid >> 5, lane = tid & 31;
#pragma unroll
    for (int r = 0; r < 4; r++) {
        int p = warp * 4 + r;
        float acc = 0.f;
#pragma unroll
        for (int j = 0; j < 8; j++)
            acc += tile[p * Dsz + lane + j * 32] * cw[lane + j * 32];
#pragma unroll
        for (int o = 16; o; o >>= 1)
            acc += __shfl_xor_sync(0xffffffffu, acc, o);
        if (lane == 0) sp[p] = acc + conv_b[0];
    }
    __syncthreads();

    float acc = 0.f;
#pragma unroll
    for (int p = 0; p < Psz; p++)
        acc += sp[p] * tile[p * Dsz + tid];

    __nv_bfloat16 h = __float2bfloat16(acc);
    __nv_bfloat16 l = __float2bfloat16(acc - __bfloat162float(h));
    __nv_bfloat16* o = aext + (size_t)blockIdx.x * KEXT;
    o[tid] = h; o[256 + tid] = l; o[512 + tid] = h;
}

// =====================================================================
// Kernel 2: mma.sync bf16 GEMM (proven: BM=128 BN=64 BK=32, 256 thr,
// 3-stage cp.async, dynamic smem, 4 blocks/SM).
// =====================================================================
#define GBM 128
#define GBN 64
#define LDE 40
#define ABYTES (128 * LDE * 2)
#define BBYTES (64 * LDE * 2)
#define STAGEB (ABYTES + BBYTES)
#define NSTEP 24
#define DYN_SMEM (3 * STAGEB)

template<bool AEXT, bool BIAS>
__global__ __launch_bounds__(256, 4)
void tgemm_mma(const __nv_bfloat16* __restrict__ Aext,
               const __nv_bfloat16* __restrict__ Bext,
               const float* __restrict__ bias, float* __restrict__ Cf,
               __nv_bfloat16* __restrict__ Ce, int Ntot)
{
    extern __shared__ __align__(16) uint8_t smem[];

    const int tid = threadIdx.x;
    const int wid = tid >> 5, lane = tid & 31;
    const int bm = blockIdx.y * GBM;
    const int bn = blockIdx.x * GBN;

    const uint32_t smBase = smem_u32(smem);

    const int warp_m = wid >> 1;
    const int warp_n = wid & 1;

    float acc[2][4][4];
#pragma unroll
    for (int i = 0; i < 2; i++)
#pragma unroll
        for (int j = 0; j < 4; j++)
#pragma unroll
            for (int q = 0; q < 4; q++) acc[i][j][q] = 0.f;

    const int arow = tid >> 2, aseg = tid & 3;
    const int lrow = lane & 15;
    const int lcol = (lane >> 4) * 16;

#define LOAD_TILE(step, buf) do {                                              \
    int kt = (step) * 32;                                                      \
    uint32_t a_s = smBase + (buf) * STAGEB;                                    \
    uint32_t b_s = a_s + ABYTES;                                               \
    CP_ASYNC16(a_s + arow * 80 + aseg * 16,                                    \
               Aext + (size_t)(bm + arow) * KEXT + kt + aseg * 8);             \
    CP_ASYNC16(a_s + (arow + 64) * 80 + aseg * 16,                             \
               Aext + (size_t)(bm + arow + 64) * KEXT + kt + aseg * 8);        \
    CP_ASYNC16(b_s + arow * 80 + aseg * 16,                                    \
               Bext + (size_t)(bn + arow) * KEXT + kt + aseg * 8);             \
} while (0)

    LOAD_TILE(0, 0); CP_COMMIT();
    LOAD_TILE(1, 1); CP_COMMIT();

    int buf = 0;
    for (int s = 0; s < NSTEP; s++) {
        if (s == NSTEP - 1) { CP_WAIT0(); } else { CP_WAIT1(); }
        __syncthreads();

        const uint32_t aBase = smBase + buf * STAGEB
                             + (warp_m * 32 + lrow) * 80 + lcol;
        const uint32_t bBase = smBase + buf * STAGEB + ABYTES
                             + (warp_n * 32 + lrow) * 80 + lcol;
#pragma unroll
        for (int ks = 0; ks < 2; ks++) {
            uint32_t a0[4], a1[4], bA[4], bB[4];
            ldmx4(a0, aBase + ks * 32);
            ldmx4(a1, aBase + 16 * 80 + ks * 32);
            ldmx4(bA, bBase + ks * 32);
            ldmx4(bB, bBase + 16 * 80 + ks * 32);
            uint32_t bf[4][2] = {{bA[0], bA[2]}, {bA[1], bA[3]},
                                 {bB[0], bB[2]}, {bB[1], bB[3]}};
#pragma unroll
            for (int fn = 0; fn < 4; fn++) {
                mma_bf16(acc[0][fn], a0, bf[fn]);
                mma_bf16(acc[1][fn], a1, bf[fn]);
            }
        }
        if (s + 2 < NSTEP) { LOAD_TILE(s + 2, (s + 2) % 3); CP_COMMIT(); }
        buf = (buf + 1 == 3) ? 0 : buf + 1;
    }
#undef LOAD_TILE

    const int qr = lane >> 2;
    const int qc = (lane & 3) * 2;
#pragma unroll
    for (int fm = 0; fm < 2; fm++) {
#pragma unroll
        for (int fn = 0; fn < 4; fn++) {
            const int m0 = bm + warp_m * 32 + fm * 16 + qr;
            const int n0 = bn + warp_n * 32 + fn * 8 + qc;
            float b0 = 0.f, b1 = 0.f;
            if (BIAS) { b0 = bias[n0]; b1 = bias[n0 + 1]; }
            float v0 = acc[fm][fn][0] + b0;
            float v1 = acc[fm][fn][1] + b1;
            float v2 = acc[fm][fn][2] + b0;
            float v3 = acc[fm][fn][3] + b1;
            if (AEXT) {
                v0 = fminf(1.f, fmaxf(-1.f, v0));
                v1 = fminf(1.f, fmaxf(-1.f, v1));
                v2 = fminf(1.f, fmaxf(-1.f, v2));
                v3 = fminf(1.f, fmaxf(-1.f, v3));
                store_ext2(Ce + (size_t)m0 * KEXT + n0, v0, v1);
                store_ext2(Ce + (size_t)(m0 + 8) * KEXT + n0, v2, v3);
            } else {
                *(float2*)&Cf[(size_t)m0 * Ntot + n0]       = make_float2(v0, v1);
                *(float2*)&Cf[(size_t)(m0 + 8) * Ntot + n0] = make_float2(v2, v3);
            }
        }
    }
}

// =====================================================================
// Kernel 3a: GRU scan for the EXT=1 launch (round-13 measured-best:
// 2-way K-split, 384 thr, gh smem, two barriers, stores in combine).
// =====================================================================
__global__ __launch_bounds__(384, 1)
void gru_scan_ext(const float* __restrict__ gates, const float* __restrict__ Whh,
                  const float* __restrict__ bhh, __nv_bfloat16* __restrict__ outE)
{
    const int dir = blockIdx.x >> 6;
    const int bpair = blockIdx.x & 63;
    const int b0 = bpair * 2;
    const int g = threadIdx.x;
    const int rr = g >> 1;          // 0..191
    const int a  = g & 1;           // k-half

    const float* Wbase = Whh + (size_t)dir * 384 * 128;
    const ulonglong2* W0 = (const ulonglong2*)(Wbase + (size_t)rr * 128 + a * 64);
    const ulonglong2* W1 = (const ulonglong2*)(Wbase + (size_t)(rr + 192) * 128 + a * 64);
    unsigned long long w0[32], w1[32];
#pragma unroll
    for (int i = 0; i < 16; i++) {
        ulonglong2 t0 = W0[i];
        ulonglong2 t1 = W1[i];
        w0[2 * i] = t0.x; w0[2 * i + 1] = t0.y;
        w1[2 * i] = t1.x; w1[2 * i + 1] = t1.y;
    }
    const float bias0 = bhh[dir * 384 + rr];
    const float bias1 = bhh[dir * 384 + rr + 192];

    __shared__ __align__(16) float h0[Hsz];
    __shared__ __align__(16) float h1[Hsz];
    __shared__ float gh0[384];
    __shared__ float gh1[384];

    if (g < Hsz) { h0[g] = 0.f; h1[g] = 0.f; }
    __syncthreads();

    const int j = g & 127;
    const int isb1 = (g >= 128 && g < 256) ? 1 : 0;
    const int bc = b0 + isb1;

    const ulonglong2* hv0 = (const ulonglong2*)(h0 + a * 64);
    const ulonglong2* hv1 = (const ulonglong2*)(h1 + a * 64);

    for (int t_ = 0; t_ < Ssz; t_++) {
        const int t = dir ? (Ssz - 1 - t_) : t_;

        float xr = 0.f, xz = 0.f, xn = 0.f;
        if (g < 256) {
            const float* gb = gates + ((size_t)(bc * Ssz + t)) * 768 + dir * 384;
            xr = gb[j];
            xz = gb[128 + j];
            xn = gb[256 + j];
        }

        unsigned long long c00 = 0ull, c01 = 0ull, c10 = 0ull, c11 = 0ull;
#pragma unroll
        for (int i = 0; i < 16; i++) {
            ulonglong2 p = hv0[i];
            ulonglong2 q = hv1[i];
            FMA2(c00, w0[2 * i],     p.x);
            FMA2(c00, w0[2 * i + 1], p.y);
            FMA2(c01, w1[2 * i],     p.x);
            FMA2(c01, w1[2 * i + 1], p.y);
            FMA2(c10, w0[2 * i],     q.x);
            FMA2(c10, w0[2 * i + 1], q.y);
            FMA2(c11, w1[2 * i],     q.x);
            FMA2(c11, w1[2 * i + 1], q.y);
        }
        float s00 = pk_lo(c00) + pk_hi(c00);
        float s01 = pk_lo(c01) + pk_hi(c01);
        float s10 = pk_lo(c10) + pk_hi(c10);
        float s11 = pk_lo(c11) + pk_hi(c11);
        s00 += __shfl_xor_sync(0xffffffffu, s00, 1);
        s01 += __shfl_xor_sync(0xffffffffu, s01, 1);
        s10 += __shfl_xor_sync(0xffffffffu, s10, 1);
        s11 += __shfl_xor_sync(0xffffffffu, s11, 1);
        if (a == 0) {
            gh0[rr]       = s00 + bias0;
            gh0[rr + 192] = s01 + bias1;
            gh1[rr]       = s10 + bias0;
            gh1[rr + 192] = s11 + bias1;
        }
        __syncthreads();

        if (g < 256) {
            float* h  = isb1 ? h1 : h0;
            float* gh = isb1 ? gh1 : gh0;
            float r = fsig(xr + gh[j]);
            float z = fsig(xz + gh[128 + j]);
            float n = ftanh(xn + r * gh[256 + j]);
            float hnew = n + z * (h[j] - n);
            h[j] = hnew;
            __nv_bfloat16 hh = __float2bfloat16(hnew);
            __nv_bfloat16 ll = __float2bfloat16(hnew - __bfloat162float(hh));
            __nv_bfloat16* o = outE + ((size_t)(bc * Ssz + t)) * KEXT
                             + dir * 128 + j;
            o[0] = hh; o[256] = ll; o[512] = hh;
        }
        __syncthreads();
    }
}

// =====================================================================
// Kernel 3b: GRU scan for the EXT=0 launch (round-13 measured-best,
// gate-fused, 256 thr, one barrier, ping-pong h) + FUSED CONTEXT SUM:
// thread (j,a) accumulates ctx[b0+a][dir*128+j] = sum_t h over the scan
// and writes it to out_ctx at the end (epilogue no longer reads states).
// =====================================================================
__global__ __launch_bounds__(256, 1)
void gru_scan_fused(const float* __restrict__ gates, const float* __restrict__ Whh,
                    const float* __restrict__ bhh, float* __restrict__ outF,
                    float* __restrict__ out_ctx)
{
    const int dir = blockIdx.x >> 6;
    const int bpair = blockIdx.x & 63;
    const int b0 = bpair * 2;
    const int g = threadIdx.x;
    const int j = g >> 1;
    const int a = g & 1;

    const float* Wb = Whh + (size_t)dir * 384 * 128;
    const ulonglong2* Wr = (const ulonglong2*)(Wb + (size_t)j * 128 + a * 64);
    const ulonglong2* Wz = (const ulonglong2*)(Wb + (size_t)(128 + j) * 128 + a * 64);
    const ulonglong2* Wn = (const ulonglong2*)(Wb + (size_t)(256 + j) * 128 + a * 64);
    unsigned long long wr[32], wz[32], wn[32];
#pragma unroll
    for (int i = 0; i < 16; i++) {
        ulonglong2 tr = Wr[i], tz = Wz[i], tn = Wn[i];
        wr[2 * i] = tr.x; wr[2 * i + 1] = tr.y;
        wz[2 * i] = tz.x; wz[2 * i + 1] = tz.y;
        wn[2 * i] = tn.x; wn[2 * i + 1] = tn.y;
    }
    const float br = bhh[dir * 384 + j];
    const float bz = bhh[dir * 384 + 128 + j];
    const float bn = bhh[dir * 384 + 256 + j];

    __shared__ __align__(16) float hsm[2][2][Hsz];

    if (g < Hsz) { hsm[0][0][g] = 0.f; hsm[0][1][g] = 0.f; }
    __syncthreads();

    float hprev0 = 0.f, hprev1 = 0.f;
    float ctxacc = 0.f;   // sum over t of this thread's own-batch h

    const float* gbase0 = gates + ((size_t)(b0 * Ssz)) * 768 + dir * 384;
    const float* gbase1 = gates + ((size_t)((b0 + 1) * Ssz)) * 768 + dir * 384;

    for (int t_ = 0; t_ < Ssz; t_++) {
        const int t = dir ? (Ssz - 1 - t_) : t_;
        const int p = t_ & 1;

        const float* gb0 = gbase0 + (size_t)t * 768;
        const float* gb1 = gbase1 + (size_t)t * 768;
        float xr0 = gb0[j], xz0 = gb0[128 + j], xn0 = gb0[256 + j];
        float xr1 = gb1[j], xz1 = gb1[128 + j], xn1 = gb1[256 + j];

        const ulonglong2* hv0 = (const ulonglong2*)(&hsm[p][0][a * 64]);
        const ulonglong2* hv1 = (const ulonglong2*)(&hsm[p][1][a * 64]);

        unsigned long long cr0 = 0ull, cz0 = 0ull, cn0 = 0ull;
        unsigned long long cr1 = 0ull, cz1 = 0ull, cn1 = 0ull;
#pragma unroll
        for (int i = 0; i < 16; i++) {
            ulonglong2 hp = hv0[i];
            ulonglong2 hq = hv1[i];
            FMA2(cr0, wr[2 * i],     hp.x); FMA2(cr0, wr[2 * i + 1], hp.y);
            FMA2(cz0, wz[2 * i],     hp.x); FMA2(cz0, wz[2 * i + 1], hp.y);
            FMA2(cn0, wn[2 * i],     hp.x); FMA2(cn0, wn[2 * i + 1], hp.y);
            FMA2(cr1, wr[2 * i],     hq.x); FMA2(cr1, wr[2 * i + 1], hq.y);
            FMA2(cz1, wz[2 * i],     hq.x); FMA2(cz1, wz[2 * i + 1], hq.y);
            FMA2(cn1, wn[2 * i],     hq.x); FMA2(cn1, wn[2 * i + 1], hq.y);
        }
        float sr0 = pk_lo(cr0) + pk_hi(cr0);
        float sz0 = pk_lo(cz0) + pk_hi(cz0);
        float sn0 = pk_lo(cn0) + pk_hi(cn0);
        float sr1 = pk_lo(cr1) + pk_hi(cr1);
        float sz1 = pk_lo(cz1) + pk_hi(cz1);
        float sn1 = pk_lo(cn1) + pk_hi(cn1);
        sr0 += __shfl_xor_sync(0xffffffffu, sr0, 1);
        sz0 += __shfl_xor_sync(0xffffffffu, sz0, 1);
        sn0 += __shfl_xor_sync(0xffffffffu, sn0, 1);
        sr1 += __shfl_xor_sync(0xffffffffu, sr1, 1);
        sz1 += __shfl_xor_sync(0xffffffffu, sz1, 1);
        sn1 += __shfl_xor_sync(0xffffffffu, sn1, 1);

        float r0 = fsig(xr0 + sr0 + br);
        float z0 = fsig(xz0 + sz0 + bz);
        float n0 = ftanh(xn0 + r0 * (sn0 + bn));
        float h0n = n0 + z0 * (hprev0 - n0);
        float r1 = fsig(xr1 + sr1 + br);
        float z1 = fsig(xz1 + sz1 + bz);
        float n1 = ftanh(xn1 + r1 * (sn1 + bn));
        float h1n = n1 + z1 * (hprev1 - n1);
        hprev0 = h0n; hprev1 = h1n;

        float hw = a ? h1n : h0n;
        ctxacc += hw;
        hsm[p ^ 1][a][j] = hw;
        const int bc = b0 + a;
        outF[((size_t)(bc * Ssz + t)) * 256 + dir * 128 + j] = hw;
        __syncthreads();
    }

    // fused context: ctx[b0+a][dir*128 + j] = sum_t h
    out_ctx[(size_t)(b0 + a) * 256 + dir * 128 + j] = ctxacc;
}

// =====================================================================
// Kernel 4: epilogue — now reads only ctx (128x256 floats).
// logits = ctx @ lin_w^T + lin_b; out = softmax; alpha = 1.
// =====================================================================
__global__ __launch_bounds__(256)
void epilogue_kernel(const float* __restrict__ ctx_in, const float* __restrict__ lin_w,
                     const float* __restrict__ lin_b, float* __restrict__ out_out,
                     float* __restrict__ out_alpha)
{
    __shared__ float ctx[256];
    __shared__ float logits[2];
    const int b = blockIdx.x;
    const int tid = threadIdx.x;

    ctx[tid] = ctx_in[(size_t)b * 256 + tid];
    if (tid < Ssz) out_alpha[(size_t)b * Ssz + tid] = 1.0f;
    __syncthreads();

    if (tid < 64) {
        const int o = tid >> 5, lane = tid & 31;
        float p = 0.f;
#pragma unroll
        for (int k = 0; k < 8; k++)
            p += ctx[lane + k * 32] * lin_w[o * 256 + lane + k * 32];
#pragma unroll
        for (int off = 16; off; off >>= 1)
            p += __shfl_xor_sync(0xffffffffu, p, off);
        if (lane == 0) logits[o] = p + lin_b[o];
    }
    __syncthreads();
    if (tid == 0) {
        float l0 = logits[0], l1 = logits[1];
        float m = fmaxf(l0, l1);
        float e0 = expf(l0 - m), e1 = expf(l1 - m);
        float inv = 1.0f / (e0 + e1);
        out_out[b * 2 + 0] = e0 * inv;
        out_out[b * 2 + 1] = e1 * inv;
    }
}

// =====================================================================
// launcher
// =====================================================================
extern "C" void kernel_launch(void* const* d_in, const int* in_sizes, int n_in,
                              void* d_out, int out_size)
{
    const float* inputs  = (const float*)d_in[0];
    const float* conv_w  = (const float*)d_in[1];
    const float* conv_b  = (const float*)d_in[2];
    const float* embed_w = (const float*)d_in[3];
    const float* Wih     = (const float*)d_in[4];
    const float* Whh     = (const float*)d_in[5];
    const float* bih     = (const float*)d_in[6];
    const float* bhh     = (const float*)d_in[7];
    const float* lin_w   = (const float*)d_in[9];
    const float* lin_b   = (const float*)d_in[10];

    float* out_base = (float*)d_out;
    const int total_expected = 256 + 8192 * 256 + 128 * 256 + 128 * 64;
    float* out_out    = out_base;
    float* out_states = out_base + 256;
    float* out_ctx    = out_states + 8192 * 256;
    float* out_alpha  = out_ctx + 128 * 256;
    const bool full = (out_size >= total_expected);

    float *px, *pctx, *pgates;
    __nv_bfloat16 *paext, *paext2, *pb0, *pb1, *pb2;
    cudaGetSymbolAddress((void**)&px, g_x);
    cudaGetSymbolAddress((void**)&pctx, g_ctx);
    cudaGetSymbolAddress((void**)&pgates, g_gates);
    cudaGetSymbolAddress((void**)&paext, g_aext);
    cudaGetSymbolAddress((void**)&paext2, g_aext2);
    cudaGetSymbolAddress((void**)&pb0, g_bext0);
    cudaGetSymbolAddress((void**)&pb1, g_bext1);
    cudaGetSymbolAddress((void**)&pb2, g_bext2);

    cudaFuncSetAttribute(tgemm_mma<true, false>,
                         cudaFuncAttributeMaxDynamicSharedMemorySize, DYN_SMEM);
    cudaFuncSetAttribute(tgemm_mma<false, true>,
                         cudaFuncAttributeMaxDynamicSharedMemorySize, DYN_SMEM);
    cudaFuncSetAttribute(tgemm_mma<true, false>,
                         cudaFuncAttributePreferredSharedMemoryCarveout, 100);
    cudaFuncSetAttribute(tgemm_mma<false, true>,
                         cudaFuncAttributePreferredSharedMemoryCarveout, 100);

    // 1) conv + weighted sum -> A_ext  AND  all 3 weight conversions
    prep_kernel<<<8192 + 1792, 256>>>(inputs, conv_w, conv_b, paext,
                                      embed_w, Wih, Wih + (size_t)2 * 384 * 256,
                                      pb0, pb1, pb2);

    // 2) embed + hardtanh (epilogue writes A_ext2)
    tgemm_mma<true, false><<<dim3(256 / GBN, 8192 / GBM), 256, DYN_SMEM>>>(
        paext, pb0, nullptr, nullptr, paext2, 256);

    // 3) layer 0: gates GEMM -> gru (gru writes A_ext for layer 1)
    tgemm_mma<false, true><<<dim3(768 / GBN, 8192 / GBM), 256, DYN_SMEM>>>(
        paext2, pb1, bih, pgates, nullptr, 768);
    gru_scan_ext<<<128, 384>>>(pgates, Whh, bhh, paext);

    // 4) layer 1: gates GEMM -> gru (writes fp32 states + fused ctx)
    tgemm_mma<false, true><<<dim3(768 / GBN, 8192 / GBM), 256, DYN_SMEM>>>(
        paext, pb2, bih + 2 * 384, pgates, nullptr, 768);
    float* states_dst = full ? out_states : px;
    float* ctx_dst    = full ? out_ctx    : pctx;
    gru_scan_fused<<<128, 256>>>(pgates, Whh + (size_t)2 * 384 * 128,
                                 bhh + 2 * 384, states_dst, ctx_dst);

    // 5) epilogue: logits + alpha from the fused ctx
    float* alpha_dst = full ? out_alpha : (pctx + 0);  // fallback: dummy sink
    if (full) {
        epilogue_kernel<<<Bsz, 256>>>(ctx_dst, lin_w, lin_b, out_out, out_alpha);
    } else {
        epilogue_kernel<<<Bsz, 256>>>(ctx_dst, lin_w, lin_b, out_out, pctx);
    }
}